// round 3
// baseline (speedup 1.0000x reference)
#include <cuda_runtime.h>
#include <cuda_bf16.h>

// Problem dims
#define BB 16
#define FF 1024
#define HH 16
#define DD 64
#define LL 8192
#define HD 1024              // HH*DD
#define NSPLIT 32
#define CHUNK 256            // LL / NSPLIT

// -------- scratch (device globals; fully rewritten every launch) ----------
__device__ __align__(16) float g_part_qkv[3 * 4 * BB * HD]; // F-split partials
__device__ __align__(16) float g_qb[BB * HD];               // q, bf16-rounded, fp32 storage
__device__ __align__(16) float g_k[BB * HD];                // k_new fp32
__device__ __align__(16) float g_v[BB * HD];                // v_new fp32
__device__ __align__(16) float g_logits[BB * HH * LL];      // fp32 logits (valid region only)
__device__ __align__(16) float g_M[BB * HH];
__device__ __align__(16) float g_S[BB * HH];
__device__ __align__(16) float g_pattn[BB * NSPLIT * HD];   // PV split partials
__device__ __align__(16) float g_attn[BB * HD];             // bf16-rounded attn, fp32 storage
__device__ __align__(16) float g_ypart[4 * BB * FF];        // out-proj hd-split partials

__device__ __forceinline__ float bfr(float x) {
    return __bfloat162float(__float2bfloat16(x)); // round-to-nearest-even, like astype(bf16)
}

// ---------------- Kernel 1: QKV projection partials -----------------------
// grid (8 colchunks, 4 fsplits, 3 matrices), 128 threads.
// Each thread owns one output column, accumulates over 256 f for all 16 batches.
__global__ void qkv_partial(const float* __restrict__ x,
                            const float* __restrict__ Wq,
                            const float* __restrict__ Wk,
                            const float* __restrict__ Wv) {
    int col = blockIdx.x * 128 + threadIdx.x;
    int f0  = blockIdx.y * 256;
    int m   = blockIdx.z;
    const float* W = (m == 0) ? Wq : (m == 1) ? Wk : Wv;

    __shared__ float xs[BB][256];
    for (int i = threadIdx.x; i < BB * 256; i += 128) {
        int b = i >> 8, f = i & 255;
        xs[b][f] = x[b * FF + f0 + f];
    }
    __syncthreads();

    float acc[BB];
#pragma unroll
    for (int b = 0; b < BB; b++) acc[b] = 0.f;

    for (int f = 0; f < 256; f++) {
        float w = W[(f0 + f) * HD + col];
#pragma unroll
        for (int b = 0; b < BB; b++) acc[b] = fmaf(xs[b][f], w, acc[b]);
    }
#pragma unroll
    for (int b = 0; b < BB; b++)
        g_part_qkv[(((m * 4 + blockIdx.y) * BB) + b) * HD + col] = acc[b];
}

// ---------------- Kernel 2: reduce partials + bias + rounding -------------
__global__ void qkv_reduce(const float* __restrict__ bq,
                           const float* __restrict__ bk,
                           const float* __restrict__ bv) {
    int e = blockIdx.x * 256 + threadIdx.x;         // 0 .. 3*BB*HD-1
    if (e >= 3 * BB * HD) return;
    int m = e / (BB * HD);
    int r = e % (BB * HD);
    int col = r % HD;
    float s = 0.f;
#pragma unroll
    for (int p = 0; p < 4; p++)
        s += g_part_qkv[((m * 4 + p) * BB) * HD + r];
    if (m == 0)      g_qb[r] = bfr(s + bq[col]);
    else if (m == 1) g_k[r]  = s + bk[col];
    else             g_v[r]  = s + bv[col];
}

// ---------------- Kernel 3: fused K-cache copy + QK logits ----------------
// grid (NSPLIT, BB), 256 threads = 8 warps. Each warp owns two cache rows per
// iteration (16 independent LDG.128 issued before any compute -> MLP_p1=16).
// Row layout: 1024 fp32 = 8 iters of (32 lanes x float4); iter j covers heads
// {2j, 2j+1}: lanes 0-15 -> head 2j, lanes 16-31 -> head 2j+1.
__global__ void key_pass(const float* __restrict__ kv_key,
                         const int* __restrict__ kv_idx,
                         float* __restrict__ okey, int do_copy) {
    int b = blockIdx.y, split = blockIdx.x;
    int tid = threadIdx.x, warp = tid >> 5, lane = tid & 31;

    __shared__ float sq[HD];
    for (int i = tid; i < HD; i += 256) sq[i] = g_qb[b * HD + i];
    __syncthreads();

    int idx = kv_idx[b] % LL;
    const float* key = kv_key + (long)b * LL * HD;
    float* ok = okey + (long)b * LL * HD;
    int l0 = split * CHUNK;
    int qoff = (lane >> 4) * 64 + (lane & 15) * 4;

    // CHUNK=256, 8 warps, stride 16: both l and l+8 always in range.
    for (int l = l0 + warp; l < l0 + CHUNK; l += 16) {
        int l2 = l + 8;
        const float* srcA = (l  == idx) ? (g_k + b * HD) : (key + (long)l  * HD);
        const float* srcB = (l2 == idx) ? (g_k + b * HD) : (key + (long)l2 * HD);
        float4 va[8], vb[8];
#pragma unroll
        for (int j = 0; j < 8; j++)
            va[j] = __ldcs((const float4*)(srcA + j * 128 + lane * 4));
#pragma unroll
        for (int j = 0; j < 8; j++)
            vb[j] = __ldcs((const float4*)(srcB + j * 128 + lane * 4));

#pragma unroll
        for (int r = 0; r < 2; r++) {
            int lr = r ? l2 : l;
            float4* vv = r ? vb : va;
            bool valid = (lr <= idx);
#pragma unroll
            for (int j = 0; j < 8; j++) {
                float4 v = vv[j];
                if (do_copy)
                    __stcs((float4*)(ok + (long)lr * HD + j * 128 + lane * 4), v);
                if (valid) {
                    const float* q = sq + j * 128 + qoff;   // already bf16-rounded
                    float p = bfr(v.x) * q[0] + bfr(v.y) * q[1] +
                              bfr(v.z) * q[2] + bfr(v.w) * q[3];
                    // reduce across each 16-lane half (one head each)
                    p += __shfl_xor_sync(0xffffffffu, p, 1);
                    p += __shfl_xor_sync(0xffffffffu, p, 2);
                    p += __shfl_xor_sync(0xffffffffu, p, 4);
                    p += __shfl_xor_sync(0xffffffffu, p, 8);
                    if ((lane & 15) == 0)
                        g_logits[(long)(b * HH + 2 * j + (lane >> 4)) * LL + lr] = p * 0.125f;
                }
            }
        }
    }
}

// ---------------- Kernel 4: per-(b,h) softmax max & sum -------------------
__global__ void softmax_stats(const int* __restrict__ kv_idx) {
    int bh = blockIdx.x;
    int b = bh >> 4;
    int n = min(kv_idx[b] % LL + 1, LL);
    const float* lg = g_logits + (long)bh * LL;
    __shared__ float red[128];

    float m = -3.402823466e38f;
    for (int l = threadIdx.x; l < n; l += 128) m = fmaxf(m, lg[l]);
    red[threadIdx.x] = m; __syncthreads();
    for (int s = 64; s > 0; s >>= 1) {
        if (threadIdx.x < s) red[threadIdx.x] = fmaxf(red[threadIdx.x], red[threadIdx.x + s]);
        __syncthreads();
    }
    float M = red[0]; __syncthreads();

    float s = 0.f;
    for (int l = threadIdx.x; l < n; l += 128) s += expf(lg[l] - M);
    red[threadIdx.x] = s; __syncthreads();
    for (int t = 64; t > 0; t >>= 1) {
        if (threadIdx.x < t) red[threadIdx.x] += red[threadIdx.x + t];
        __syncthreads();
    }
    if (threadIdx.x == 0) { g_M[bh] = M; g_S[bh] = red[0]; }
}

// ---------------- Kernel 5: fused V-cache copy + P*V ----------------------
__global__ void value_pass(const float* __restrict__ kv_value,
                           const int* __restrict__ kv_idx,
                           float* __restrict__ oval, int do_copy) {
    int b = blockIdx.y, split = blockIdx.x;
    int tid = threadIdx.x, warp = tid >> 5, lane = tid & 31;

    __shared__ float sM[HH], sS[HH];
    __shared__ __align__(16) float sacc[8][HD];
    if (tid < HH) { sM[tid] = g_M[b * HH + tid]; sS[tid] = g_S[b * HH + tid]; }
    __syncthreads();

    int idx = kv_idx[b] % LL;
    const float* val = kv_value + (long)b * LL * HD;
    float* ov = oval + (long)b * LL * HD;
    int l0 = split * CHUNK;

    float4 acc[8];
#pragma unroll
    for (int j = 0; j < 8; j++) acc[j] = make_float4(0.f, 0.f, 0.f, 0.f);

    for (int l = l0 + warp; l < l0 + CHUNK; l += 8) {
        const float* src = (l == idx) ? (g_v + b * HD) : (val + (long)l * HD);
        bool valid = (l <= idx);
        float p = 0.f;
        if (valid && lane < HH)
            p = bfr(expf(g_logits[(long)(b * HH + lane) * LL + l] - sM[lane]) / sS[lane]);
#pragma unroll
        for (int j = 0; j < 8; j++) {
            float4 v = __ldcs((const float4*)(src + j * 128 + lane * 4));
            if (do_copy)
                __stcs((float4*)(ov + (long)l * HD + j * 128 + lane * 4), v);
            float ph = __shfl_sync(0xffffffffu, p, 2 * j + (lane >> 4));
            if (valid) {
                acc[j].x = fmaf(ph, bfr(v.x), acc[j].x);
                acc[j].y = fmaf(ph, bfr(v.y), acc[j].y);
                acc[j].z = fmaf(ph, bfr(v.z), acc[j].z);
                acc[j].w = fmaf(ph, bfr(v.w), acc[j].w);
            }
        }
    }
    // deterministic block reduction: warp accs -> shared -> per-thread sum
#pragma unroll
    for (int j = 0; j < 8; j++)
        *(float4*)&sacc[warp][j * 128 + lane * 4] = acc[j];
    __syncthreads();

    int e0 = tid * 4;
    float4 r = make_float4(0.f, 0.f, 0.f, 0.f);
#pragma unroll
    for (int w = 0; w < 8; w++) {
        float4 t = *(float4*)&sacc[w][e0];
        r.x += t.x; r.y += t.y; r.z += t.z; r.w += t.w;
    }
    *(float4*)&g_pattn[((long)b * NSPLIT + split) * HD + e0] = r;
}

// ---------------- Kernel 6: reduce PV splits, round attn to bf16 ----------
__global__ void attn_reduce() {
    int e = blockIdx.x * 256 + threadIdx.x;   // 0 .. BB*HD-1
    if (e >= BB * HD) return;
    int b = e / HD, c = e % HD;
    float s = 0.f;
#pragma unroll
    for (int sp = 0; sp < NSPLIT; sp++)
        s += g_pattn[((long)b * NSPLIT + sp) * HD + c];
    g_attn[e] = bfr(s);   // reference's bf16-out einsum
}

// ---------------- Kernel 7: output projection partials --------------------
__global__ void proj_partial(const float* __restrict__ Wo) {
    int col = blockIdx.x * 128 + threadIdx.x;
    int hd0 = blockIdx.y * 256;

    __shared__ float xs[BB][256];
    for (int i = threadIdx.x; i < BB * 256; i += 128) {
        int b = i >> 8, h = i & 255;
        xs[b][h] = g_attn[b * HD + hd0 + h];
    }
    __syncthreads();

    float acc[BB];
#pragma unroll
    for (int b = 0; b < BB; b++) acc[b] = 0.f;
    for (int h = 0; h < 256; h++) {
        float w = Wo[(hd0 + h) * FF + col];
#pragma unroll
        for (int b = 0; b < BB; b++) acc[b] = fmaf(xs[b][h], w, acc[b]);
    }
#pragma unroll
    for (int b = 0; b < BB; b++)
        g_ypart[(blockIdx.y * BB + b) * FF + col] = acc[b];
}

// ---------------- Kernel 8: final y + new_idx -----------------------------
__global__ void finalize(const float* __restrict__ bo,
                         const int* __restrict__ kv_idx,
                         float* __restrict__ oy,
                         float* __restrict__ oidx, int has_tail) {
    int e = blockIdx.x * 256 + threadIdx.x;   // 0 .. BB*FF-1
    if (e >= BB * FF) return;
    int b = e / FF, col = e % FF;
    float s = bo[col];
#pragma unroll
    for (int p = 0; p < 4; p++) s += g_ypart[(p * BB + b) * FF + col];
    oy[e] = s;
    if (has_tail && e < BB) oidx[e] = (float)(kv_idx[e] + 1);
}

// ---------------------------------------------------------------------------
extern "C" void kernel_launch(void* const* d_in, const int* in_sizes, int n_in,
                              void* d_out, int out_size) {
    const float* x        = (const float*)d_in[0];
    const float* kv_key   = (const float*)d_in[1];
    const float* kv_value = (const float*)d_in[2];
    const int*   kv_idx   = (const int*)d_in[3];
    const float* Wq = (const float*)d_in[4];
    const float* bq = (const float*)d_in[5];
    const float* Wk = (const float*)d_in[6];
    const float* bk = (const float*)d_in[7];
    const float* Wv = (const float*)d_in[8];
    const float* bv = (const float*)d_in[9];
    const float* Wo = (const float*)d_in[10];
    const float* bo = (const float*)d_in[11];

    float* out = (float*)d_out;
    const long Y_ELEMS  = (long)BB * FF;                 // 16384
    const long KV_ELEMS = (long)BB * LL * HD;            // 134217728
    float* oy   = out;
    float* okey = out + Y_ELEMS;
    float* oval = okey + KV_ELEMS;
    float* oidx = oval + KV_ELEMS;

    // If out only holds y, skip cache copies / idx tail (defensive).
    long need = Y_ELEMS + 2 * KV_ELEMS + BB;
    int full = ((long)out_size >= need) ? 1 : 0;
    if (!full) { okey = oy; oval = oy; oidx = oy; }      // guarded stores anyway

    qkv_partial<<<dim3(8, 4, 3), 128>>>(x, Wq, Wk, Wv);
    qkv_reduce<<<(3 * BB * HD + 255) / 256, 256>>>(bq, bk, bv);
    key_pass<<<dim3(NSPLIT, BB), 256>>>(kv_key, kv_idx, okey, full);
    softmax_stats<<<BB * HH, 128>>>(kv_idx);
    value_pass<<<dim3(NSPLIT, BB), 256>>>(kv_value, kv_idx, oval, full);
    attn_reduce<<<(BB * HD + 255) / 256, 256>>>();
    proj_partial<<<dim3(8, 4), 128>>>(Wo);
    finalize<<<(BB * FF + 255) / 256, 256>>>(bo, kv_idx, oy, oidx, full);
}

// round 5
// speedup vs baseline: 1.0726x; 1.0726x over previous
#include <cuda_runtime.h>
#include <cuda_bf16.h>

// Problem dims
#define BB 16
#define FF 1024
#define HH 16
#define DD 64
#define LL 8192
#define HD 1024              // HH*DD
#define NSPLIT 64
#define CHUNK 128            // LL / NSPLIT
#define FSPLIT 8             // qkv f-splits (chunk 128)
#define PSPLIT 16            // out-proj hd-splits (chunk 64)

// -------- scratch (device globals; fully rewritten every launch) ----------
__device__ __align__(16) float g_part_qkv[3 * FSPLIT * BB * HD]; // F-split partials
__device__ __align__(16) float g_qb[BB * HD];               // q, bf16-rounded, fp32 storage
__device__ __align__(16) float g_k[BB * HD];                // k_new fp32
__device__ __align__(16) float g_v[BB * HD];                // v_new fp32
__device__ __align__(16) float g_logits[BB * HH * LL];      // fp32 logits (valid region only)
__device__ __align__(16) float g_M[BB * HH];
__device__ __align__(16) float g_S[BB * HH];
__device__ __align__(16) float g_pattn[BB * NSPLIT * HD];   // PV split partials
__device__ __align__(16) float g_attn[BB * HD];             // bf16-rounded attn, fp32 storage
__device__ __align__(16) float g_ypart[PSPLIT * BB * FF];   // out-proj hd-split partials

__device__ __forceinline__ float bfr(float x) {
    return __bfloat162float(__float2bfloat16(x)); // round-to-nearest-even, like astype(bf16)
}

// ---------------- Kernel 1: QKV projection partials -----------------------
// grid (8 colchunks, FSPLIT fsplits, 3 matrices), 128 threads.
__global__ void qkv_partial(const float* __restrict__ x,
                            const float* __restrict__ Wq,
                            const float* __restrict__ Wk,
                            const float* __restrict__ Wv) {
    int col = blockIdx.x * 128 + threadIdx.x;
    int f0  = blockIdx.y * 128;
    int m   = blockIdx.z;
    const float* W = (m == 0) ? Wq : (m == 1) ? Wk : Wv;

    __shared__ float xs[BB][128];
    for (int i = threadIdx.x; i < BB * 128; i += 128) {
        int b = i >> 7, f = i & 127;
        xs[b][f] = x[b * FF + f0 + f];
    }
    __syncthreads();

    float acc[BB];
#pragma unroll
    for (int b = 0; b < BB; b++) acc[b] = 0.f;

    for (int f = 0; f < 128; f++) {
        float w = W[(f0 + f) * HD + col];
#pragma unroll
        for (int b = 0; b < BB; b++) acc[b] = fmaf(xs[b][f], w, acc[b]);
    }
#pragma unroll
    for (int b = 0; b < BB; b++)
        g_part_qkv[(((m * FSPLIT + blockIdx.y) * BB) + b) * HD + col] = acc[b];
}

// ---------------- Kernel 2: reduce partials + bias + rounding -------------
__global__ void qkv_reduce(const float* __restrict__ bq,
                           const float* __restrict__ bk,
                           const float* __restrict__ bv) {
    int e = blockIdx.x * 256 + threadIdx.x;         // 0 .. 3*BB*HD-1
    if (e >= 3 * BB * HD) return;
    int m = e / (BB * HD);
    int r = e % (BB * HD);
    int col = r % HD;
    float s = 0.f;
#pragma unroll
    for (int p = 0; p < FSPLIT; p++)
        s += g_part_qkv[((m * FSPLIT + p) * BB) * HD + r];
    if (m == 0)      g_qb[r] = bfr(s + bq[col]);
    else if (m == 1) g_k[r]  = s + bk[col];
    else             g_v[r]  = s + bv[col];
}

// ---------------- Kernel 3: fused K-cache copy + QK logits ----------------
// Launched TWICE (b0=0, b0=8); launch #4 of the sequence is the second half
// (ncu capture slot). grid (NSPLIT, 8), 256 threads = 8 warps. Each warp owns
// two cache rows per iteration (16 front-batched LDG.128 -> MLP_p1=16).
// Row layout: 1024 fp32 = 8 iters of (32 lanes x float4); iter j covers heads
// {2j, 2j+1}: lanes 0-15 -> head 2j, lanes 16-31 -> head 2j+1.
__global__ void key_pass(const float* __restrict__ kv_key,
                         const int* __restrict__ kv_idx,
                         float* __restrict__ okey, int do_copy, int b0) {
    int b = blockIdx.y + b0, split = blockIdx.x;
    int tid = threadIdx.x, warp = tid >> 5, lane = tid & 31;

    __shared__ float sq[HD];
    for (int i = tid; i < HD; i += 256) sq[i] = g_qb[b * HD + i];
    __syncthreads();

    int idx = kv_idx[b] % LL;
    const float* key = kv_key + (long)b * LL * HD;
    float* ok = okey + (long)b * LL * HD;
    int l0 = split * CHUNK;
    int qoff = (lane >> 4) * 64 + (lane & 15) * 4;

    // CHUNK=128, 8 warps, stride 16: both l and l+8 always in range.
    for (int l = l0 + warp; l < l0 + CHUNK; l += 16) {
        int l2 = l + 8;
        const float* srcA = (l  == idx) ? (g_k + b * HD) : (key + (long)l  * HD);
        const float* srcB = (l2 == idx) ? (g_k + b * HD) : (key + (long)l2 * HD);
        float4 va[8], vb[8];
#pragma unroll
        for (int j = 0; j < 8; j++)
            va[j] = __ldcs((const float4*)(srcA + j * 128 + lane * 4));
#pragma unroll
        for (int j = 0; j < 8; j++)
            vb[j] = __ldcs((const float4*)(srcB + j * 128 + lane * 4));

#pragma unroll
        for (int r = 0; r < 2; r++) {
            int lr = r ? l2 : l;
            float4* vv = r ? vb : va;
            bool valid = (lr <= idx);
#pragma unroll
            for (int j = 0; j < 8; j++) {
                float4 v = vv[j];
                if (do_copy)
                    __stcs((float4*)(ok + (long)lr * HD + j * 128 + lane * 4), v);
                if (valid) {
                    const float* q = sq + j * 128 + qoff;   // already bf16-rounded
                    float p = bfr(v.x) * q[0] + bfr(v.y) * q[1] +
                              bfr(v.z) * q[2] + bfr(v.w) * q[3];
                    // reduce across each 16-lane half (one head each)
                    p += __shfl_xor_sync(0xffffffffu, p, 1);
                    p += __shfl_xor_sync(0xffffffffu, p, 2);
                    p += __shfl_xor_sync(0xffffffffu, p, 4);
                    p += __shfl_xor_sync(0xffffffffu, p, 8);
                    if ((lane & 15) == 0)
                        g_logits[(long)(b * HH + 2 * j + (lane >> 4)) * LL + lr] = p * 0.125f;
                }
            }
        }
    }
}

// ---------------- Kernel 4: per-(b,h) softmax max & sum -------------------
__global__ void softmax_stats(const int* __restrict__ kv_idx) {
    int bh = blockIdx.x;
    int b = bh >> 4;
    int n = min(kv_idx[b] % LL + 1, LL);
    const float* lg = g_logits + (long)bh * LL;
    __shared__ float red[128];

    float m = -3.402823466e38f;
    for (int l = threadIdx.x; l < n; l += 128) m = fmaxf(m, lg[l]);
    red[threadIdx.x] = m; __syncthreads();
    for (int s = 64; s > 0; s >>= 1) {
        if (threadIdx.x < s) red[threadIdx.x] = fmaxf(red[threadIdx.x], red[threadIdx.x + s]);
        __syncthreads();
    }
    float M = red[0]; __syncthreads();

    float s = 0.f;
    for (int l = threadIdx.x; l < n; l += 128) s += expf(lg[l] - M);
    red[threadIdx.x] = s; __syncthreads();
    for (int t = 64; t > 0; t >>= 1) {
        if (threadIdx.x < t) red[threadIdx.x] += red[threadIdx.x + t];
        __syncthreads();
    }
    if (threadIdx.x == 0) { g_M[bh] = M; g_S[bh] = red[0]; }
}

// ---------------- Kernel 5: fused V-cache copy + P*V ----------------------
// Launched TWICE (b0=0, b0=8). grid (NSPLIT, 8), 256 threads = 8 warps.
__global__ void value_pass(const float* __restrict__ kv_value,
                           const int* __restrict__ kv_idx,
                           float* __restrict__ oval, int do_copy, int b0) {
    int b = blockIdx.y + b0, split = blockIdx.x;
    int tid = threadIdx.x, warp = tid >> 5, lane = tid & 31;

    __shared__ float sM[HH], sS[HH];
    __shared__ __align__(16) float sacc[8][HD];
    if (tid < HH) { sM[tid] = g_M[b * HH + tid]; sS[tid] = g_S[b * HH + tid]; }
    __syncthreads();

    int idx = kv_idx[b] % LL;
    const float* val = kv_value + (long)b * LL * HD;
    float* ov = oval + (long)b * LL * HD;
    int l0 = split * CHUNK;

    float4 acc[8];
#pragma unroll
    for (int j = 0; j < 8; j++) acc[j] = make_float4(0.f, 0.f, 0.f, 0.f);

    for (int l = l0 + warp; l < l0 + CHUNK; l += 8) {
        const float* src = (l == idx) ? (g_v + b * HD) : (val + (long)l * HD);
        bool valid = (l <= idx);
        float p = 0.f;
        if (valid && lane < HH)
            p = bfr(expf(g_logits[(long)(b * HH + lane) * LL + l] - sM[lane]) / sS[lane]);
#pragma unroll
        for (int j = 0; j < 8; j++) {
            float4 v = __ldcs((const float4*)(src + j * 128 + lane * 4));
            if (do_copy)
                __stcs((float4*)(ov + (long)l * HD + j * 128 + lane * 4), v);
            float ph = __shfl_sync(0xffffffffu, p, 2 * j + (lane >> 4));
            if (valid) {
                acc[j].x = fmaf(ph, bfr(v.x), acc[j].x);
                acc[j].y = fmaf(ph, bfr(v.y), acc[j].y);
                acc[j].z = fmaf(ph, bfr(v.z), acc[j].z);
                acc[j].w = fmaf(ph, bfr(v.w), acc[j].w);
            }
        }
    }
    // deterministic block reduction: warp accs -> shared -> per-thread sum
#pragma unroll
    for (int j = 0; j < 8; j++)
        *(float4*)&sacc[warp][j * 128 + lane * 4] = acc[j];
    __syncthreads();

    int e0 = tid * 4;
    float4 r = make_float4(0.f, 0.f, 0.f, 0.f);
#pragma unroll
    for (int w = 0; w < 8; w++) {
        float4 t = *(float4*)&sacc[w][e0];
        r.x += t.x; r.y += t.y; r.z += t.z; r.w += t.w;
    }
    *(float4*)&g_pattn[((long)b * NSPLIT + split) * HD + e0] = r;
}

// ---------------- Kernel 6: reduce PV splits, round attn to bf16 ----------
__global__ void attn_reduce() {
    int e = blockIdx.x * 256 + threadIdx.x;   // 0 .. BB*HD-1
    if (e >= BB * HD) return;
    int b = e / HD, c = e % HD;
    float s = 0.f;
#pragma unroll
    for (int sp = 0; sp < NSPLIT; sp++)
        s += g_pattn[((long)b * NSPLIT + sp) * HD + c];
    g_attn[e] = bfr(s);   // reference's bf16-out einsum
}

// ---------------- Kernel 7: output projection partials --------------------
// grid (8 colchunks, PSPLIT hd-splits of 64), 128 threads -> 128 blocks.
__global__ void proj_partial(const float* __restrict__ Wo) {
    int col = blockIdx.x * 128 + threadIdx.x;
    int hd0 = blockIdx.y * 64;

    __shared__ float xs[BB][64];
    for (int i = threadIdx.x; i < BB * 64; i += 128) {
        int b = i >> 6, h = i & 63;
        xs[b][h] = g_attn[b * HD + hd0 + h];
    }
    __syncthreads();

    float acc[BB];
#pragma unroll
    for (int b = 0; b < BB; b++) acc[b] = 0.f;
    for (int h = 0; h < 64; h++) {
        float w = Wo[(hd0 + h) * FF + col];
#pragma unroll
        for (int b = 0; b < BB; b++) acc[b] = fmaf(xs[b][h], w, acc[b]);
    }
#pragma unroll
    for (int b = 0; b < BB; b++)
        g_ypart[(blockIdx.y * BB + b) * FF + col] = acc[b];
}

// ---------------- Kernel 8: final y + new_idx -----------------------------
__global__ void finalize(const float* __restrict__ bo,
                         const int* __restrict__ kv_idx,
                         float* __restrict__ oy,
                         float* __restrict__ oidx, int has_tail) {
    int e = blockIdx.x * 256 + threadIdx.x;   // 0 .. BB*FF-1
    if (e >= BB * FF) return;
    int b = e / FF, col = e % FF;
    float s = bo[col];
#pragma unroll
    for (int p = 0; p < PSPLIT; p++) s += g_ypart[(p * BB + b) * FF + col];
    oy[e] = s;
    if (has_tail && e < BB) oidx[e] = (float)(kv_idx[e] + 1);
}

// ---------------------------------------------------------------------------
extern "C" void kernel_launch(void* const* d_in, const int* in_sizes, int n_in,
                              void* d_out, int out_size) {
    const float* x        = (const float*)d_in[0];
    const float* kv_key   = (const float*)d_in[1];
    const float* kv_value = (const float*)d_in[2];
    const int*   kv_idx   = (const int*)d_in[3];
    const float* Wq = (const float*)d_in[4];
    const float* bq = (const float*)d_in[5];
    const float* Wk = (const float*)d_in[6];
    const float* bk = (const float*)d_in[7];
    const float* Wv = (const float*)d_in[8];
    const float* bv = (const float*)d_in[9];
    const float* Wo = (const float*)d_in[10];
    const float* bo = (const float*)d_in[11];

    float* out = (float*)d_out;
    const long Y_ELEMS  = (long)BB * FF;                 // 16384
    const long KV_ELEMS = (long)BB * LL * HD;            // 134217728
    float* oy   = out;
    float* okey = out + Y_ELEMS;
    float* oval = okey + KV_ELEMS;
    float* oidx = oval + KV_ELEMS;

    // If out only holds y, skip cache copies / idx tail (defensive).
    long need = Y_ELEMS + 2 * KV_ELEMS + BB;
    int full = ((long)out_size >= need) ? 1 : 0;
    if (!full) { okey = oy; oval = oy; oidx = oy; }      // guarded stores anyway

    qkv_partial<<<dim3(8, FSPLIT, 3), 128>>>(x, Wq, Wk, Wv);          // #1
    qkv_reduce<<<(3 * BB * HD + 255) / 256, 256>>>(bq, bk, bv);       // #2
    key_pass<<<dim3(NSPLIT, 8), 256>>>(kv_key, kv_idx, okey, full, 0);   // #3
    key_pass<<<dim3(NSPLIT, 8), 256>>>(kv_key, kv_idx, okey, full, 8);   // #4 capture
    softmax_stats<<<BB * HH, 128>>>(kv_idx);                          // #5
    value_pass<<<dim3(NSPLIT, 8), 256>>>(kv_value, kv_idx, oval, full, 0); // #6
    value_pass<<<dim3(NSPLIT, 8), 256>>>(kv_value, kv_idx, oval, full, 8); // #7
    attn_reduce<<<(BB * HD + 255) / 256, 256>>>();                    // #8
    proj_partial<<<dim3(8, PSPLIT), 128>>>(Wo);                       // #9
    finalize<<<(BB * FF + 255) / 256, 256>>>(bo, kv_idx, oy, oidx, full); // #10
}

// round 7
// speedup vs baseline: 1.2907x; 1.2034x over previous
#include <cuda_runtime.h>
#include <cuda_bf16.h>

// Problem dims
#define BB 16
#define FF 1024
#define HH 16
#define DD 64
#define LL 8192
#define HD 1024              // HH*DD
#define WPB 216              // warps per batch in streaming kernels (27 blocks x 8)
#define VSPLIT 27            // value partial slots per batch
#define FSPLIT 8             // qkv f-splits (chunk 128)
#define PSPLIT 16            // out-proj hd-splits (chunk 64)

// -------- scratch (device globals; fully rewritten every launch) ----------
__device__ __align__(16) float g_part_qkv[3 * FSPLIT * BB * HD]; // F-split partials
__device__ __align__(16) float g_qb[BB * HD];               // q, bf16-rounded, fp32 storage
__device__ __align__(16) float g_k[BB * HD];                // k_new fp32
__device__ __align__(16) float g_v[BB * HD];                // v_new fp32
__device__ __align__(16) float g_logits[BB * HH * LL];      // fp32 logits (valid region only)
__device__ __align__(16) float g_M[BB * HH];
__device__ __align__(16) float g_S[BB * HH];
__device__ __align__(16) float g_pattn[BB * VSPLIT * HD];   // PV split partials
__device__ __align__(16) float g_attn[BB * HD];             // bf16-rounded attn, fp32 storage
__device__ __align__(16) float g_ypart[PSPLIT * BB * FF];   // out-proj hd-split partials

__device__ __forceinline__ float bfr(float x) {
    return __bfloat162float(__float2bfloat16(x)); // round-to-nearest-even, like astype(bf16)
}

// ---------------- Kernel 1: QKV projection partials -----------------------
// grid (8 colchunks, FSPLIT fsplits, 3 matrices), 128 threads.
__global__ void qkv_partial(const float* __restrict__ x,
                            const float* __restrict__ Wq,
                            const float* __restrict__ Wk,
                            const float* __restrict__ Wv) {
    int col = blockIdx.x * 128 + threadIdx.x;
    int f0  = blockIdx.y * 128;
    int m   = blockIdx.z;
    const float* W = (m == 0) ? Wq : (m == 1) ? Wk : Wv;

    __shared__ float xs[BB][128];
    for (int i = threadIdx.x; i < BB * 128; i += 128) {
        int b = i >> 7, f = i & 127;
        xs[b][f] = x[b * FF + f0 + f];
    }
    __syncthreads();

    float acc[BB];
#pragma unroll
    for (int b = 0; b < BB; b++) acc[b] = 0.f;

#pragma unroll 4
    for (int f = 0; f < 128; f++) {
        float w = W[(f0 + f) * HD + col];
#pragma unroll
        for (int b = 0; b < BB; b++) acc[b] = fmaf(xs[b][f], w, acc[b]);
    }
#pragma unroll
    for (int b = 0; b < BB; b++)
        g_part_qkv[(((m * FSPLIT + blockIdx.y) * BB) + b) * HD + col] = acc[b];
}

// ---------------- Kernel 2: reduce partials + bias + rounding -------------
__global__ void qkv_reduce(const float* __restrict__ bq,
                           const float* __restrict__ bk,
                           const float* __restrict__ bv) {
    int e = blockIdx.x * 256 + threadIdx.x;         // 0 .. 3*BB*HD-1
    if (e >= 3 * BB * HD) return;
    int m = e / (BB * HD);
    int r = e % (BB * HD);
    int col = r % HD;
    float s = 0.f;
#pragma unroll
    for (int p = 0; p < FSPLIT; p++)
        s += g_part_qkv[((m * FSPLIT + p) * BB) * HD + r];
    if (m == 0)      g_qb[r] = bfr(s + bq[col]);
    else if (m == 1) g_k[r]  = s + bk[col];
    else             g_v[r]  = s + bv[col];
}

// ---------------- Kernel 3: fused K-cache copy + QK logits ----------------
// Launched TWICE (b0=0, b0=8); launch #4 of the sequence (capture slot) is the
// second half. grid (27, 8) = 216 blocks <= one wave at occ 3 (no wave tail).
// Warp w in [0,216) per batch grid-strides rows l = w + 216*i, processing two
// rows per loop (16 front-batched LDG.128 -> MLP 16).
// Row layout: 1024 fp32 = 8 iters of (32 lanes x float4); iter j covers heads
// {2j, 2j+1}: lanes 0-15 -> head 2j, lanes 16-31 -> head 2j+1.
__global__ void __launch_bounds__(256, 3)
key_pass(const float* __restrict__ kv_key,
         const int* __restrict__ kv_idx,
         float* __restrict__ okey, int do_copy, int b0) {
    int b = blockIdx.y + b0;
    int w = blockIdx.x * 8 + (threadIdx.x >> 5);   // 0..215 within batch
    int lane = threadIdx.x & 31;

    __shared__ float sq[HD];
    for (int i = threadIdx.x; i < HD; i += 256) sq[i] = g_qb[b * HD + i];
    __syncthreads();

    int idx = kv_idx[b] % LL;
    const float* key = kv_key + (long)b * LL * HD;
    float* ok = okey + (long)b * LL * HD;
    int qoff = (lane >> 4) * 64 + (lane & 15) * 4;

    for (int l = w; l < LL; l += 2 * WPB) {
        int l2 = l + WPB;
        bool has2 = (l2 < LL);
        const float* srcA = (l  == idx) ? (g_k + b * HD) : (key + (long)l  * HD);
        const float* srcB = (l2 == idx) ? (g_k + b * HD) : (key + (long)l2 * HD);
        float4 va[8], vb[8];
#pragma unroll
        for (int j = 0; j < 8; j++)
            va[j] = __ldcs((const float4*)(srcA + j * 128 + lane * 4));
        if (has2) {
#pragma unroll
            for (int j = 0; j < 8; j++)
                vb[j] = __ldcs((const float4*)(srcB + j * 128 + lane * 4));
        }

#pragma unroll
        for (int r = 0; r < 2; r++) {
            int lr = r ? l2 : l;
            if (r && !has2) break;
            float4* vv = r ? vb : va;
            bool valid = (lr <= idx);
#pragma unroll
            for (int j = 0; j < 8; j++) {
                float4 v = vv[j];
                if (do_copy)
                    __stcs((float4*)(ok + (long)lr * HD + j * 128 + lane * 4), v);
                if (valid) {
                    const float* q = sq + j * 128 + qoff;   // already bf16-rounded
                    float p = bfr(v.x) * q[0] + bfr(v.y) * q[1] +
                              bfr(v.z) * q[2] + bfr(v.w) * q[3];
                    // reduce across each 16-lane half (one head each)
                    p += __shfl_xor_sync(0xffffffffu, p, 1);
                    p += __shfl_xor_sync(0xffffffffu, p, 2);
                    p += __shfl_xor_sync(0xffffffffu, p, 4);
                    p += __shfl_xor_sync(0xffffffffu, p, 8);
                    if ((lane & 15) == 0)
                        g_logits[(long)(b * HH + 2 * j + (lane >> 4)) * LL + lr] = p * 0.125f;
                }
            }
        }
    }
}

// ---------------- Kernel 4: per-(b,h) softmax max & sum -------------------
__global__ void softmax_stats(const int* __restrict__ kv_idx) {
    int bh = blockIdx.x;
    int b = bh >> 4;
    int n = min(kv_idx[b] % LL + 1, LL);
    const float* lg = g_logits + (long)bh * LL;
    __shared__ float red[128];

    float m = -3.402823466e38f;
    for (int l = threadIdx.x; l < n; l += 128) m = fmaxf(m, lg[l]);
    red[threadIdx.x] = m; __syncthreads();
    for (int s = 64; s > 0; s >>= 1) {
        if (threadIdx.x < s) red[threadIdx.x] = fmaxf(red[threadIdx.x], red[threadIdx.x + s]);
        __syncthreads();
    }
    float M = red[0]; __syncthreads();

    float s = 0.f;
    for (int l = threadIdx.x; l < n; l += 128) s += expf(lg[l] - M);
    red[threadIdx.x] = s; __syncthreads();
    for (int t = 64; t > 0; t >>= 1) {
        if (threadIdx.x < t) red[threadIdx.x] += red[threadIdx.x + t];
        __syncthreads();
    }
    if (threadIdx.x == 0) { g_M[bh] = M; g_S[bh] = red[0]; }
}

// ---------------- Kernel 5: fused V-cache copy + P*V ----------------------
// Single launch, grid (27, 16) = 432 blocks <= one wave at occ 3.
// Warp w in [0,216) per batch grid-strides rows l = w + 216*i.
__global__ void __launch_bounds__(256, 3)
value_pass(const float* __restrict__ kv_value,
           const int* __restrict__ kv_idx,
           float* __restrict__ oval, int do_copy) {
    int b = blockIdx.y;
    int tid = threadIdx.x, warp = tid >> 5, lane = tid & 31;
    int w = blockIdx.x * 8 + warp;                 // 0..215 within batch

    __shared__ float sM[HH], sS[HH];
    __shared__ __align__(16) float sacc[8][HD];
    if (tid < HH) { sM[tid] = g_M[b * HH + tid]; sS[tid] = g_S[b * HH + tid]; }
    __syncthreads();

    int idx = kv_idx[b] % LL;
    const float* val = kv_value + (long)b * LL * HD;
    float* ov = oval + (long)b * LL * HD;

    float4 acc[8];
#pragma unroll
    for (int j = 0; j < 8; j++) acc[j] = make_float4(0.f, 0.f, 0.f, 0.f);

    for (int l = w; l < LL; l += WPB) {
        const float* src = (l == idx) ? (g_v + b * HD) : (val + (long)l * HD);
        bool valid = (l <= idx);
        float p = 0.f;
        if (valid && lane < HH)
            p = bfr(expf(g_logits[(long)(b * HH + lane) * LL + l] - sM[lane]) / sS[lane]);
#pragma unroll
        for (int j = 0; j < 8; j++) {
            float4 v = __ldcs((const float4*)(src + j * 128 + lane * 4));
            if (do_copy)
                __stcs((float4*)(ov + (long)l * HD + j * 128 + lane * 4), v);
            float ph = __shfl_sync(0xffffffffu, p, 2 * j + (lane >> 4));
            if (valid) {
                acc[j].x = fmaf(ph, bfr(v.x), acc[j].x);
                acc[j].y = fmaf(ph, bfr(v.y), acc[j].y);
                acc[j].z = fmaf(ph, bfr(v.z), acc[j].z);
                acc[j].w = fmaf(ph, bfr(v.w), acc[j].w);
            }
        }
    }
    // deterministic block reduction: warp accs -> shared -> per-thread sum
#pragma unroll
    for (int j = 0; j < 8; j++)
        *(float4*)&sacc[warp][j * 128 + lane * 4] = acc[j];
    __syncthreads();

    int e0 = tid * 4;
    float4 r = make_float4(0.f, 0.f, 0.f, 0.f);
#pragma unroll
    for (int wi = 0; wi < 8; wi++) {
        float4 t = *(float4*)&sacc[wi][e0];
        r.x += t.x; r.y += t.y; r.z += t.z; r.w += t.w;
    }
    *(float4*)&g_pattn[((long)b * VSPLIT + blockIdx.x) * HD + e0] = r;
}

// ---------------- Kernel 6: reduce PV splits, round attn to bf16 ----------
__global__ void attn_reduce() {
    int e = blockIdx.x * 256 + threadIdx.x;   // 0 .. BB*HD-1
    if (e >= BB * HD) return;
    int b = e / HD, c = e % HD;
    float s = 0.f;
#pragma unroll
    for (int sp = 0; sp < VSPLIT; sp++)
        s += g_pattn[((long)b * VSPLIT + sp) * HD + c];
    g_attn[e] = bfr(s);   // reference's bf16-out einsum
}

// ---------------- Kernel 7: output projection partials --------------------
// grid (8 colchunks, PSPLIT hd-splits of 64), 128 threads -> 128 blocks.
__global__ void proj_partial(const float* __restrict__ Wo) {
    int col = blockIdx.x * 128 + threadIdx.x;
    int hd0 = blockIdx.y * 64;

    __shared__ float xs[BB][64];
    for (int i = threadIdx.x; i < BB * 64; i += 128) {
        int b = i >> 6, h = i & 63;
        xs[b][h] = g_attn[b * HD + hd0 + h];
    }
    __syncthreads();

    float acc[BB];
#pragma unroll
    for (int b = 0; b < BB; b++) acc[b] = 0.f;
#pragma unroll 4
    for (int h = 0; h < 64; h++) {
        float w = Wo[(hd0 + h) * FF + col];
#pragma unroll
        for (int b = 0; b < BB; b++) acc[b] = fmaf(xs[b][h], w, acc[b]);
    }
#pragma unroll
    for (int b = 0; b < BB; b++)
        g_ypart[(blockIdx.y * BB + b) * FF + col] = acc[b];
}

// ---------------- Kernel 8: final y + new_idx -----------------------------
__global__ void finalize(const float* __restrict__ bo,
                         const int* __restrict__ kv_idx,
                         float* __restrict__ oy,
                         float* __restrict__ oidx, int has_tail) {
    int e = blockIdx.x * 256 + threadIdx.x;   // 0 .. BB*FF-1
    if (e >= BB * FF) return;
    int b = e / FF, col = e % FF;
    float s = bo[col];
#pragma unroll
    for (int p = 0; p < PSPLIT; p++) s += g_ypart[(p * BB + b) * FF + col];
    oy[e] = s;
    if (has_tail && e < BB) oidx[e] = (float)(kv_idx[e] + 1);
}

// ---------------------------------------------------------------------------
extern "C" void kernel_launch(void* const* d_in, const int* in_sizes, int n_in,
                              void* d_out, int out_size) {
    const float* x        = (const float*)d_in[0];
    const float* kv_key   = (const float*)d_in[1];
    const float* kv_value = (const float*)d_in[2];
    const int*   kv_idx   = (const int*)d_in[3];
    const float* Wq = (const float*)d_in[4];
    const float* bq = (const float*)d_in[5];
    const float* Wk = (const float*)d_in[6];
    const float* bk = (const float*)d_in[7];
    const float* Wv = (const float*)d_in[8];
    const float* bv = (const float*)d_in[9];
    const float* Wo = (const float*)d_in[10];
    const float* bo = (const float*)d_in[11];

    float* out = (float*)d_out;
    const long Y_ELEMS  = (long)BB * FF;                 // 16384
    const long KV_ELEMS = (long)BB * LL * HD;            // 134217728
    float* oy   = out;
    float* okey = out + Y_ELEMS;
    float* oval = okey + KV_ELEMS;
    float* oidx = oval + KV_ELEMS;

    // If out only holds y, skip cache copies / idx tail (defensive).
    long need = Y_ELEMS + 2 * KV_ELEMS + BB;
    int full = ((long)out_size >= need) ? 1 : 0;
    if (!full) { okey = oy; oval = oy; oidx = oy; }      // guarded stores anyway

    qkv_partial<<<dim3(8, FSPLIT, 3), 128>>>(x, Wq, Wk, Wv);            // #1
    qkv_reduce<<<(3 * BB * HD + 255) / 256, 256>>>(bq, bk, bv);         // #2
    key_pass<<<dim3(27, 8), 256>>>(kv_key, kv_idx, okey, full, 0);      // #3
    key_pass<<<dim3(27, 8), 256>>>(kv_key, kv_idx, okey, full, 8);      // #4 capture
    softmax_stats<<<BB * HH, 128>>>(kv_idx);                            // #5
    value_pass<<<dim3(27, 16), 256>>>(kv_value, kv_idx, oval, full);    // #6
    attn_reduce<<<(BB * HD + 255) / 256, 256>>>();                      // #7
    proj_partial<<<dim3(8, PSPLIT), 128>>>(Wo);                         // #8
    finalize<<<(BB * FF + 255) / 256, 256>>>(bo, kv_idx, oy, oidx, full); // #9
}